// round 3
// baseline (speedup 1.0000x reference)
#include <cuda_runtime.h>

#define S_   512
#define H_   16
#define D_   24
#define DS_  384
#define CZ_  128
#define EPS_ 1e-5f
#define SCALE_ 0.20412414523193152f   // 24^-0.5

// -------- scratch (no allocations allowed) --------
__device__ float g_qt[H_*S_*D_];      // [H][S][D], q pre-scaled by D^-0.5
__device__ float g_kt[H_*S_*D_];
__device__ float g_vt[H_*S_*D_];
__device__ float g_g[S_*DS_];
__device__ float g_o[S_*DS_];
__device__ float g_bias[H_*S_*S_];    // includes seq_mask

// ============================================================
// bias = LN(z) @ z_w^T + mask -> g_bias[H][S][S]
// Block = 128-row tile of z. No shuffles in hot path:
//  A) stage 128x128 z tile into smem (coalesced)
//  B) LN: 2 threads/row (64 ch each, one shfl pair-combine), y in place
//  C) mini-GEMM C[128,16] = Y @ zw^T, thread = 4 rows x 2 heads
// ============================================================
#define LDX_ 132    // padded row stride in smem floats

extern __shared__ float smx[];
__global__ __launch_bounds__(256) void bias_kernel(
    const float* __restrict__ z, const float* __restrict__ mask,
    const float* __restrict__ lnw, const float* __restrict__ lnb,
    const float* __restrict__ zw)
{
    const int tid = threadIdx.x;
    const int r0  = blockIdx.x * 128;       // flat row base
    const int i_  = r0 >> 9;                // z row (query i)
    const int j0  = r0 & 511;               // key j base (tile stays in one i)

    // ---- A: stage z tile ----
    #pragma unroll
    for (int it = 0; it < 16; it++) {
        const int l = tid + it*256;
        const int row = l >> 5, c4 = l & 31;
        *(float4*)&smx[row*LDX_ + c4*4] =
            *(const float4*)&z[(size_t)(r0 + row)*CZ_ + c4*4];
    }
    __syncthreads();

    // ---- B: layernorm, y written in place ----
    {
        const int row  = tid >> 1;
        const int base = (tid & 1) * 64;
        float* xr = &smx[row*LDX_ + base];
        float4 v[16];
        float sum = 0.f, ssq = 0.f;
        #pragma unroll
        for (int c = 0; c < 16; c++) {
            v[c] = *(const float4*)&xr[c*4];
            sum += v[c].x + v[c].y + v[c].z + v[c].w;
            ssq += v[c].x*v[c].x + v[c].y*v[c].y + v[c].z*v[c].z + v[c].w*v[c].w;
        }
        sum += __shfl_xor_sync(0xffffffffu, sum, 1);
        ssq += __shfl_xor_sync(0xffffffffu, ssq, 1);
        const float mu   = sum * (1.f/CZ_);
        const float var_ = ssq * (1.f/CZ_) - mu*mu;
        const float rinv = rsqrtf(var_ + EPS_);
        #pragma unroll
        for (int c = 0; c < 16; c++) {
            const float4 w4 = *(const float4*)&lnw[base + c*4];
            const float4 b4 = *(const float4*)&lnb[base + c*4];
            float4 y;
            y.x = (v[c].x - mu)*rinv*w4.x + b4.x;
            y.y = (v[c].y - mu)*rinv*w4.y + b4.y;
            y.z = (v[c].z - mu)*rinv*w4.z + b4.z;
            y.w = (v[c].w - mu)*rinv*w4.w + b4.w;
            *(float4*)&xr[c*4] = y;
        }
    }
    __syncthreads();

    // ---- C: C[128,16] = Y[128,128] @ zw[16,128]^T ----
    {
        const int rg = tid & 31;        // row group: rows rg*4 .. rg*4+3
        const int hg = tid >> 5;        // head group: heads 2hg, 2hg+1 (warp-uniform)
        const float* zw0 = &zw[(2*hg  )*CZ_];
        const float* zw1 = &zw[(2*hg+1)*CZ_];
        float acc[4][2] = {};
        #pragma unroll
        for (int c4 = 0; c4 < 32; c4++) {
            const float4 w0 = *(const float4*)&zw0[c4*4];   // warp-uniform broadcast
            const float4 w1 = *(const float4*)&zw1[c4*4];
            #pragma unroll
            for (int i = 0; i < 4; i++) {
                const float4 y = *(const float4*)&smx[(rg*4 + i)*LDX_ + c4*4];
                acc[i][0] += y.x*w0.x + y.y*w0.y + y.z*w0.z + y.w*w0.w;
                acc[i][1] += y.x*w1.x + y.y*w1.y + y.z*w1.z + y.w*w1.w;
            }
        }
        #pragma unroll
        for (int i = 0; i < 4; i++) {
            const int j = j0 + rg*4 + i;
            const float mk = mask[j];
            g_bias[((2*hg  )*S_ + i_)*S_ + j] = acc[i][0] + mk;
            g_bias[((2*hg+1)*S_ + i_)*S_ + j] = acc[i][1] + mk;
        }
    }
}

// ============================================================
// QKVG GEMMs: C[M,N] = s[M,K] * W[N,K]^T, 32x64 tiles, 2x4 microtile
// q/k/v stored head-major transposed, q pre-scaled; g gets sigmoid.
// ============================================================
__global__ __launch_bounds__(256) void gemm_qkvg_kernel(
    const float* __restrict__ s,
    const float* __restrict__ qw, const float* __restrict__ qb,
    const float* __restrict__ kw, const float* __restrict__ vw,
    const float* __restrict__ gw)
{
    __shared__ float As[32][34];
    __shared__ float Bs[32][68];
    const int b   = blockIdx.x;
    const int var = b / 96;
    const int r   = b % 96;
    const int n0  = (r % 6) * 64;
    const int m0  = (r / 6) * 32;
    const float* W = (var==0)?qw:(var==1)?kw:(var==2)?vw:gw;
    const int tid = threadIdx.x;
    const int tx = tid & 15, ty = tid >> 4;
    const int lk = tid & 31, lm = tid >> 5;
    float acc[2][4] = {};

    for (int k0 = 0; k0 < DS_; k0 += 32) {
        #pragma unroll
        for (int i = 0; i < 4; i++)
            As[lk][lm + 8*i] = s[(m0 + lm + 8*i)*DS_ + k0 + lk];
        #pragma unroll
        for (int i = 0; i < 8; i++)
            Bs[lk][lm + 8*i] = W[(n0 + lm + 8*i)*DS_ + k0 + lk];
        __syncthreads();
        #pragma unroll
        for (int kk = 0; kk < 32; kk++) {
            const float2 a = *(const float2*)&As[kk][ty*2];
            const float4 bv = *(const float4*)&Bs[kk][tx*4];
            acc[0][0] += a.x*bv.x; acc[0][1] += a.x*bv.y; acc[0][2] += a.x*bv.z; acc[0][3] += a.x*bv.w;
            acc[1][0] += a.y*bv.x; acc[1][1] += a.y*bv.y; acc[1][2] += a.y*bv.z; acc[1][3] += a.y*bv.w;
        }
        __syncthreads();
    }

    const int col = n0 + tx*4;
    #pragma unroll
    for (int i = 0; i < 2; i++) {
        const int row = m0 + ty*2 + i;
        float4 rv = make_float4(acc[i][0], acc[i][1], acc[i][2], acc[i][3]);
        if (var == 0) {
            rv.x += qb[col]; rv.y += qb[col+1]; rv.z += qb[col+2]; rv.w += qb[col+3];
            rv.x *= SCALE_; rv.y *= SCALE_; rv.z *= SCALE_; rv.w *= SCALE_;
        }
        if (var == 3) {
            rv.x = 1.f/(1.f+__expf(-rv.x));
            rv.y = 1.f/(1.f+__expf(-rv.y));
            rv.z = 1.f/(1.f+__expf(-rv.z));
            rv.w = 1.f/(1.f+__expf(-rv.w));
            *(float4*)&g_g[row*DS_ + col] = rv;
        } else {
            const int hh = col / D_;
            const int dd = col - hh*D_;
            float* dst = (var==0) ? g_qt : (var==1) ? g_kt : g_vt;
            *(float4*)&dst[(hh*S_ + row)*D_ + dd] = rv;
        }
    }
}

// ============================================================
// attention: block = (head, 32 q-rows). Scores-only smem (65.7KB,
// 3 blocks/SM). K/V read straight from L2 (head-major, coalesced).
// ============================================================
extern __shared__ float smem_attn[];
__global__ __launch_bounds__(256) void attn_kernel()
{
    float* sc = smem_attn;               // [32][513]
    const int h    = blockIdx.y;
    const int qi0  = blockIdx.x * 32;
    const int tid  = threadIdx.x;
    const int lane = tid & 31;
    const int w    = tid >> 5;
    const int qib  = w * 4;

    float qr[4][24];
    #pragma unroll
    for (int i = 0; i < 4; i++) {
        const float4* qp = (const float4*)&g_qt[(h*S_ + qi0 + qib + i)*D_];
        #pragma unroll
        for (int c = 0; c < 6; c++) {
            float4 v = qp[c];
            qr[i][c*4+0] = v.x; qr[i][c*4+1] = v.y; qr[i][c*4+2] = v.z; qr[i][c*4+3] = v.w;
        }
    }

    const float* bias_row = &g_bias[(h*S_ + qi0 + qib)*S_];
    #pragma unroll 1
    for (int u = 0; u < 16; u++) {
        const int kj = lane + 32*u;
        const float4* kp = (const float4*)&g_kt[(h*S_ + kj)*D_];
        float a0 = 0.f, a1 = 0.f, a2 = 0.f, a3 = 0.f;
        #pragma unroll
        for (int c = 0; c < 6; c++) {
            const float4 kv = kp[c];
            a0 += qr[0][c*4]*kv.x + qr[0][c*4+1]*kv.y + qr[0][c*4+2]*kv.z + qr[0][c*4+3]*kv.w;
            a1 += qr[1][c*4]*kv.x + qr[1][c*4+1]*kv.y + qr[1][c*4+2]*kv.z + qr[1][c*4+3]*kv.w;
            a2 += qr[2][c*4]*kv.x + qr[2][c*4+1]*kv.y + qr[2][c*4+2]*kv.z + qr[2][c*4+3]*kv.w;
            a3 += qr[3][c*4]*kv.x + qr[3][c*4+1]*kv.y + qr[3][c*4+2]*kv.z + qr[3][c*4+3]*kv.w;
        }
        sc[(qib+0)*513 + kj] = a0 + bias_row[0*S_ + kj];
        sc[(qib+1)*513 + kj] = a1 + bias_row[1*S_ + kj];
        sc[(qib+2)*513 + kj] = a2 + bias_row[2*S_ + kj];
        sc[(qib+3)*513 + kj] = a3 + bias_row[3*S_ + kj];
    }
    __syncthreads();

    #pragma unroll 1
    for (int rr = 0; rr < 4; rr++) {
        float* p = &sc[(qib + rr)*513];
        float mx = -1e30f;
        #pragma unroll
        for (int t = 0; t < 16; t++) mx = fmaxf(mx, p[lane + 32*t]);
        #pragma unroll
        for (int m = 16; m >= 1; m >>= 1) mx = fmaxf(mx, __shfl_xor_sync(0xffffffffu, mx, m));
        float e[16];
        float sum = 0.f;
        #pragma unroll
        for (int t = 0; t < 16; t++) { e[t] = __expf(p[lane + 32*t] - mx); sum += e[t]; }
        #pragma unroll
        for (int m = 16; m >= 1; m >>= 1) sum += __shfl_xor_sync(0xffffffffu, sum, m);
        const float rinv = 1.f / sum;
        #pragma unroll
        for (int t = 0; t < 16; t++) p[lane + 32*t] = e[t]*rinv;
    }
    __syncthreads();

    {
        const int qi = lane;
        const int db = w * 3;
        float a0 = 0.f, a1 = 0.f, a2 = 0.f;
        const float* p = &sc[qi*513];
        const float* vb = &g_vt[h*S_*D_ + db];
        #pragma unroll 8
        for (int kj = 0; kj < S_; kj++) {
            const float pv = p[kj];
            a0 += pv * vb[kj*D_ + 0];
            a1 += pv * vb[kj*D_ + 1];
            a2 += pv * vb[kj*D_ + 2];
        }
        float* op = &g_o[(qi0 + qi)*DS_ + h*D_ + db];
        op[0] = a0; op[1] = a1; op[2] = a2;
    }
}

// ============================================================
// out = (o * g) @ o_w^T  : 16x64 tiles -> 192 blocks
// ============================================================
__global__ __launch_bounds__(256) void gemm_out_kernel(
    const float* __restrict__ W, float* __restrict__ C)
{
    __shared__ float As[32][17];
    __shared__ float Bs[32][68];
    const int n0 = blockIdx.x*64, m0 = blockIdx.y*16;
    const int tid = threadIdx.x;
    const int tx = tid & 15, ty = tid >> 4;
    const int lk = tid & 31, lm = tid >> 5;
    float acc[4] = {};

    for (int k0 = 0; k0 < DS_; k0 += 32) {
        #pragma unroll
        for (int i = 0; i < 2; i++) {
            const int m = lm + 8*i;
            const int ai = (m0 + m)*DS_ + k0 + lk;
            As[lk][m] = g_o[ai] * g_g[ai];
        }
        #pragma unroll
        for (int i = 0; i < 8; i++)
            Bs[lk][lm + 8*i] = W[(n0 + lm + 8*i)*DS_ + k0 + lk];
        __syncthreads();
        #pragma unroll
        for (int kk = 0; kk < 32; kk++) {
            const float a = As[kk][ty];
            const float4 b = *(const float4*)&Bs[kk][tx*4];
            acc[0] += a*b.x; acc[1] += a*b.y; acc[2] += a*b.z; acc[3] += a*b.w;
        }
        __syncthreads();
    }
    *(float4*)&C[(m0 + ty)*DS_ + n0 + tx*4] = make_float4(acc[0], acc[1], acc[2], acc[3]);
}

// ============================================================
extern "C" void kernel_launch(void* const* d_in, const int* in_sizes, int n_in,
                              void* d_out, int out_size)
{
    const float* s   = (const float*)d_in[0];
    const float* z   = (const float*)d_in[1];
    const float* msk = (const float*)d_in[2];
    const float* qw  = (const float*)d_in[3];
    const float* qb  = (const float*)d_in[4];
    const float* kw  = (const float*)d_in[5];
    const float* vw  = (const float*)d_in[6];
    const float* gw  = (const float*)d_in[7];
    const float* ow  = (const float*)d_in[8];
    const float* lnw = (const float*)d_in[9];
    const float* lnb = (const float*)d_in[10];
    const float* zw  = (const float*)d_in[11];
    float* out = (float*)d_out;

    const int smem_bias = 128*LDX_*4;   // 67584 B
    const int smem_attn_b = 32*513*4;   // 65664 B
    cudaFuncSetAttribute(bias_kernel, cudaFuncAttributeMaxDynamicSharedMemorySize, smem_bias);
    cudaFuncSetAttribute(attn_kernel, cudaFuncAttributeMaxDynamicSharedMemorySize, smem_attn_b);

    gemm_qkvg_kernel<<<384, 256>>>(s, qw, qb, kw, vw, gw);
    bias_kernel<<<2048, 256, smem_bias>>>(z, msk, lnw, lnb, zw);
    attn_kernel<<<dim3(16, 16), 256, smem_attn_b>>>();
    gemm_out_kernel<<<dim3(6, 32), 256>>>(ow, out);
}

// round 4
// speedup vs baseline: 1.6866x; 1.6866x over previous
#include <cuda_runtime.h>

#define S_   512
#define H_   16
#define D_   24
#define DS_  384
#define CZ_  128
#define EPS_ 1e-5f
#define SCALE_ 0.20412414523193152f   // 24^-0.5

// -------- scratch (no allocations allowed) --------
__device__ float g_qt[H_*S_*D_];      // [H][S][D], q pre-scaled by D^-0.5
__device__ float g_kt[H_*S_*D_];
__device__ float g_vt[H_*S_*D_];
__device__ float g_g[S_*DS_];
__device__ float g_o[S_*DS_];
__device__ float g_bias[H_*S_*S_];    // includes seq_mask

// ============================================================
// bias = LN(z) @ z_w^T + mask -> g_bias[H][S][S]
// Block = 128-row z tile.
//  A) stage z tile + zw + mask into smem (coalesced)
//  B) LN: 2 threads/row, one shfl pair-combine, y in place
//  C) mini-GEMM: warp = (row-group rg = w&3, head-half hg = w>>2),
//     lane = row within group -> LDS stride 132 floats -> bank 4*lane
//     (conflict-free per LDS.128 phase). zw/mask reads = uniform bcast.
// ============================================================
#define LDX_ 132    // padded row stride in smem floats

extern __shared__ float smx[];
__global__ __launch_bounds__(256) void bias_kernel(
    const float* __restrict__ z, const float* __restrict__ mask,
    const float* __restrict__ lnw, const float* __restrict__ lnb,
    const float* __restrict__ zw)
{
    float* Y  = smx;                  // 128*132
    float* ZW = smx + 128*LDX_;       // 16*128
    float* MS = ZW + 16*CZ_;          // 128
    const int tid = threadIdx.x;
    const int lane = tid & 31;
    const int r0  = blockIdx.x * 128;
    const int i_  = r0 >> 9;
    const int j0  = r0 & 511;

    // ---- A: stage ----
    #pragma unroll
    for (int it = 0; it < 16; it++) {
        const int l = tid + it*256;
        const int row = l >> 5, c4 = l & 31;
        *(float4*)&Y[row*LDX_ + c4*4] =
            *(const float4*)&z[(size_t)(r0 + row)*CZ_ + c4*4];
    }
    #pragma unroll
    for (int it = 0; it < 2; it++)
        ((float4*)ZW)[tid + it*256] = ((const float4*)zw)[tid + it*256];
    if (tid < 32) ((float4*)MS)[tid] = ((const float4*)(mask + j0))[tid];
    __syncthreads();

    // ---- B: layernorm in place ----
    {
        const int row  = tid >> 1;
        const int base = (tid & 1) * 64;
        float* xr = &Y[row*LDX_ + base];
        float sum = 0.f, ssq = 0.f;
        #pragma unroll
        for (int c = 0; c < 16; c++) {
            const float4 v = *(const float4*)&xr[c*4];
            sum += v.x + v.y + v.z + v.w;
            ssq += v.x*v.x + v.y*v.y + v.z*v.z + v.w*v.w;
        }
        sum += __shfl_xor_sync(0xffffffffu, sum, 1);
        ssq += __shfl_xor_sync(0xffffffffu, ssq, 1);
        const float mu   = sum * (1.f/CZ_);
        const float var_ = ssq * (1.f/CZ_) - mu*mu;
        const float rinv = rsqrtf(var_ + EPS_);
        #pragma unroll
        for (int c = 0; c < 16; c++) {
            const float4 v  = *(const float4*)&xr[c*4];
            const float4 w4 = *(const float4*)&lnw[base + c*4];
            const float4 b4 = *(const float4*)&lnb[base + c*4];
            float4 y;
            y.x = (v.x - mu)*rinv*w4.x + b4.x;
            y.y = (v.y - mu)*rinv*w4.y + b4.y;
            y.z = (v.z - mu)*rinv*w4.z + b4.z;
            y.w = (v.w - mu)*rinv*w4.w + b4.w;
            *(float4*)&xr[c*4] = y;
        }
    }
    __syncthreads();

    // ---- C: C[128,16] = Y @ zw^T ----
    {
        const int w  = tid >> 5;
        const int rg = w & 3;           // row group
        const int hb = (w >> 2) * 8;    // head base (0 or 8)
        const int row = rg*32 + lane;
        const float* yr = &Y[row*LDX_];
        float acc[8] = {};
        #pragma unroll 4
        for (int c4 = 0; c4 < 32; c4++) {
            const float4 y = *(const float4*)&yr[c4*4];
            #pragma unroll
            for (int h = 0; h < 8; h++) {
                const float4 wv = *(const float4*)&ZW[(hb + h)*CZ_ + c4*4];
                acc[h] += y.x*wv.x + y.y*wv.y + y.z*wv.z + y.w*wv.w;
            }
        }
        const float mk = MS[row];
        const int j = j0 + row;
        #pragma unroll
        for (int h = 0; h < 8; h++)
            g_bias[((hb + h)*S_ + i_)*S_ + j] = acc[h] + mk;
    }
}

// ============================================================
// QKVG GEMMs: 32x64 tiles, 2x4 microtile, reg double-buffered.
// ============================================================
__global__ __launch_bounds__(256) void gemm_qkvg_kernel(
    const float* __restrict__ s,
    const float* __restrict__ qw, const float* __restrict__ qb,
    const float* __restrict__ kw, const float* __restrict__ vw,
    const float* __restrict__ gw)
{
    __shared__ float As[32][34];
    __shared__ float Bs[32][68];
    const int b   = blockIdx.x;
    const int var = b / 96;
    const int r   = b % 96;
    const int n0  = (r % 6) * 64;
    const int m0  = (r / 6) * 32;
    const float* W = (var==0)?qw:(var==1)?kw:(var==2)?vw:gw;
    const int tid = threadIdx.x;
    const int tx = tid & 15, ty = tid >> 4;
    const int lk = tid & 31, lm = tid >> 5;
    float acc[2][4] = {};
    float pa[4], pb[8];

    #pragma unroll
    for (int i = 0; i < 4; i++) pa[i] = s[(m0 + lm + 8*i)*DS_ + lk];
    #pragma unroll
    for (int i = 0; i < 8; i++) pb[i] = W[(n0 + lm + 8*i)*DS_ + lk];

    for (int k0 = 0; k0 < DS_; k0 += 32) {
        #pragma unroll
        for (int i = 0; i < 4; i++) As[lk][lm + 8*i] = pa[i];
        #pragma unroll
        for (int i = 0; i < 8; i++) Bs[lk][lm + 8*i] = pb[i];
        __syncthreads();
        if (k0 + 32 < DS_) {
            #pragma unroll
            for (int i = 0; i < 4; i++) pa[i] = s[(m0 + lm + 8*i)*DS_ + k0 + 32 + lk];
            #pragma unroll
            for (int i = 0; i < 8; i++) pb[i] = W[(n0 + lm + 8*i)*DS_ + k0 + 32 + lk];
        }
        #pragma unroll
        for (int kk = 0; kk < 32; kk++) {
            const float2 a = *(const float2*)&As[kk][ty*2];
            const float4 bv = *(const float4*)&Bs[kk][tx*4];
            acc[0][0] += a.x*bv.x; acc[0][1] += a.x*bv.y; acc[0][2] += a.x*bv.z; acc[0][3] += a.x*bv.w;
            acc[1][0] += a.y*bv.x; acc[1][1] += a.y*bv.y; acc[1][2] += a.y*bv.z; acc[1][3] += a.y*bv.w;
        }
        __syncthreads();
    }

    const int col = n0 + tx*4;
    #pragma unroll
    for (int i = 0; i < 2; i++) {
        const int row = m0 + ty*2 + i;
        float4 rv = make_float4(acc[i][0], acc[i][1], acc[i][2], acc[i][3]);
        if (var == 0) {
            rv.x += qb[col]; rv.y += qb[col+1]; rv.z += qb[col+2]; rv.w += qb[col+3];
            rv.x *= SCALE_; rv.y *= SCALE_; rv.z *= SCALE_; rv.w *= SCALE_;
        }
        if (var == 3) {
            rv.x = 1.f/(1.f+__expf(-rv.x));
            rv.y = 1.f/(1.f+__expf(-rv.y));
            rv.z = 1.f/(1.f+__expf(-rv.z));
            rv.w = 1.f/(1.f+__expf(-rv.w));
            *(float4*)&g_g[row*DS_ + col] = rv;
        } else {
            const int hh = col / D_;
            const int dd = col - hh*D_;
            float* dst = (var==0) ? g_qt : (var==1) ? g_kt : g_vt;
            *(float4*)&dst[(hh*S_ + row)*D_ + dd] = rv;
        }
    }
}

// ============================================================
// attention: block = (head, 32 q-rows). K/V staged in smem per
// 128-kj tile (layout [kj][28]: lane stride 28 -> conflict-free).
// PV: V reads are warp-uniform smem broadcasts; p reads bank
// (lane+kj)%32 conflict-free.
// ============================================================
extern __shared__ float sma[];
__global__ __launch_bounds__(256) void attn_kernel()
{
    float* sc = sma;                    // [32][513]
    float* kv = sma + 32*513;           // [128][28] staging (K then V)
    const int h    = blockIdx.y;
    const int qi0  = blockIdx.x * 32;
    const int tid  = threadIdx.x;
    const int lane = tid & 31;
    const int w    = tid >> 5;
    const int qib  = w * 4;

    // q rows in registers
    float qr[4][24];
    #pragma unroll
    for (int i = 0; i < 4; i++) {
        const float4* qp = (const float4*)&g_qt[(h*S_ + qi0 + qib + i)*D_];
        #pragma unroll
        for (int c = 0; c < 6; c++) {
            float4 v = qp[c];
            qr[i][c*4+0] = v.x; qr[i][c*4+1] = v.y; qr[i][c*4+2] = v.z; qr[i][c*4+3] = v.w;
        }
    }

    const float* bias_row = &g_bias[(h*S_ + qi0 + qib)*S_];

    // ---- scores over 4 kj-tiles of 128 ----
    #pragma unroll 1
    for (int tt = 0; tt < 4; tt++) {
        // stage K tile: 128 rows x 24 floats = 768 float4, contiguous in g_kt
        const float4* src = (const float4*)&g_kt[(h*S_ + tt*128)*D_];
        #pragma unroll
        for (int it = 0; it < 3; it++) {
            const int f = tid + it*256;
            const float4 v = src[f];
            const int e0 = f*4;
            const int kjl = e0 / 24, d0 = e0 - kjl*24;
            *(float4*)&kv[kjl*28 + d0] = v;
        }
        __syncthreads();

        #pragma unroll
        for (int ul = 0; ul < 4; ul++) {
            const int kjl = lane + 32*ul;
            const int kj  = tt*128 + kjl;
            const float* kp = &kv[kjl*28];
            float a0 = 0.f, a1 = 0.f, a2 = 0.f, a3 = 0.f;
            #pragma unroll
            for (int c = 0; c < 6; c++) {
                const float4 k4 = *(const float4*)&kp[c*4];
                a0 += qr[0][c*4]*k4.x + qr[0][c*4+1]*k4.y + qr[0][c*4+2]*k4.z + qr[0][c*4+3]*k4.w;
                a1 += qr[1][c*4]*k4.x + qr[1][c*4+1]*k4.y + qr[1][c*4+2]*k4.z + qr[1][c*4+3]*k4.w;
                a2 += qr[2][c*4]*k4.x + qr[2][c*4+1]*k4.y + qr[2][c*4+2]*k4.z + qr[2][c*4+3]*k4.w;
                a3 += qr[3][c*4]*k4.x + qr[3][c*4+1]*k4.y + qr[3][c*4+2]*k4.z + qr[3][c*4+3]*k4.w;
            }
            sc[(qib+0)*513 + kj] = a0 + bias_row[0*S_ + kj];
            sc[(qib+1)*513 + kj] = a1 + bias_row[1*S_ + kj];
            sc[(qib+2)*513 + kj] = a2 + bias_row[2*S_ + kj];
            sc[(qib+3)*513 + kj] = a3 + bias_row[3*S_ + kj];
        }
        __syncthreads();
    }

    // ---- softmax: warp owns its 4 rows ----
    #pragma unroll 1
    for (int rr = 0; rr < 4; rr++) {
        float* p = &sc[(qib + rr)*513];
        float mx = -1e30f;
        #pragma unroll
        for (int t = 0; t < 16; t++) mx = fmaxf(mx, p[lane + 32*t]);
        #pragma unroll
        for (int m = 16; m >= 1; m >>= 1) mx = fmaxf(mx, __shfl_xor_sync(0xffffffffu, mx, m));
        float e[16];
        float sum = 0.f;
        #pragma unroll
        for (int t = 0; t < 16; t++) { e[t] = __expf(p[lane + 32*t] - mx); sum += e[t]; }
        #pragma unroll
        for (int m = 16; m >= 1; m >>= 1) sum += __shfl_xor_sync(0xffffffffu, sum, m);
        const float rinv = 1.f / sum;
        #pragma unroll
        for (int t = 0; t < 16; t++) p[lane + 32*t] = e[t]*rinv;
    }
    __syncthreads();

    // ---- PV over 4 kj-tiles; thread = (qi=lane, d-group w<6) ----
    {
        const int qi = lane;
        const int dg = w;                   // warps 0..5 active
        float acc[4] = {};
        #pragma unroll 1
        for (int tt = 0; tt < 4; tt++) {
            const float4* src = (const float4*)&g_vt[(h*S_ + tt*128)*D_];
            #pragma unroll
            for (int it = 0; it < 3; it++) {
                const int f = tid + it*256;
                const float4 v = src[f];
                const int e0 = f*4;
                const int kjl = e0 / 24, d0 = e0 - kjl*24;
                *(float4*)&kv[kjl*28 + d0] = v;
            }
            __syncthreads();
            if (dg < 6) {
                const float* prow = &sc[qi*513 + tt*128];
                #pragma unroll 4
                for (int kjl = 0; kjl < 128; kjl++) {
                    const float pv = prow[kjl];
                    const float4 v4 = *(const float4*)&kv[kjl*28 + dg*4];
                    acc[0] += pv*v4.x; acc[1] += pv*v4.y; acc[2] += pv*v4.z; acc[3] += pv*v4.w;
                }
            }
            __syncthreads();
        }
        if (dg < 6)
            *(float4*)&g_o[(qi0 + qi)*DS_ + h*D_ + dg*4] =
                make_float4(acc[0], acc[1], acc[2], acc[3]);
    }
}

// ============================================================
// out = (o * g) @ o_w^T : 16x64 tiles, reg double-buffered
// ============================================================
__global__ __launch_bounds__(256) void gemm_out_kernel(
    const float* __restrict__ W, float* __restrict__ C)
{
    __shared__ float As[32][17];
    __shared__ float Bs[32][68];
    const int n0 = blockIdx.x*64, m0 = blockIdx.y*16;
    const int tid = threadIdx.x;
    const int tx = tid & 15, ty = tid >> 4;
    const int lk = tid & 31, lm = tid >> 5;
    float acc[4] = {};
    float pa[2], pb[8];

    #pragma unroll
    for (int i = 0; i < 2; i++) {
        const int ai = (m0 + lm + 8*i)*DS_ + lk;
        pa[i] = g_o[ai] * g_g[ai];
    }
    #pragma unroll
    for (int i = 0; i < 8; i++) pb[i] = W[(n0 + lm + 8*i)*DS_ + lk];

    for (int k0 = 0; k0 < DS_; k0 += 32) {
        #pragma unroll
        for (int i = 0; i < 2; i++) As[lk][lm + 8*i] = pa[i];
        #pragma unroll
        for (int i = 0; i < 8; i++) Bs[lk][lm + 8*i] = pb[i];
        __syncthreads();
        if (k0 + 32 < DS_) {
            #pragma unroll
            for (int i = 0; i < 2; i++) {
                const int ai = (m0 + lm + 8*i)*DS_ + k0 + 32 + lk;
                pa[i] = g_o[ai] * g_g[ai];
            }
            #pragma unroll
            for (int i = 0; i < 8; i++) pb[i] = W[(n0 + lm + 8*i)*DS_ + k0 + 32 + lk];
        }
        #pragma unroll
        for (int kk = 0; kk < 32; kk++) {
            const float a = As[kk][ty];
            const float4 b = *(const float4*)&Bs[kk][tx*4];
            acc[0] += a*b.x; acc[1] += a*b.y; acc[2] += a*b.z; acc[3] += a*b.w;
        }
        __syncthreads();
    }
    *(float4*)&C[(m0 + ty)*DS_ + n0 + tx*4] = make_float4(acc[0], acc[1], acc[2], acc[3]);
}

// ============================================================
extern "C" void kernel_launch(void* const* d_in, const int* in_sizes, int n_in,
                              void* d_out, int out_size)
{
    const float* s   = (const float*)d_in[0];
    const float* z   = (const float*)d_in[1];
    const float* msk = (const float*)d_in[2];
    const float* qw  = (const float*)d_in[3];
    const float* qb  = (const float*)d_in[4];
    const float* kw  = (const float*)d_in[5];
    const float* vw  = (const float*)d_in[6];
    const float* gw  = (const float*)d_in[7];
    const float* ow  = (const float*)d_in[8];
    const float* lnw = (const float*)d_in[9];
    const float* lnb = (const float*)d_in[10];
    const float* zw  = (const float*)d_in[11];
    float* out = (float*)d_out;

    const int smem_bias = (128*LDX_ + 16*CZ_ + 128) * 4;   // 76352 B
    const int smem_attn = (32*513 + 128*28) * 4;           // 80000 B
    cudaFuncSetAttribute(bias_kernel, cudaFuncAttributeMaxDynamicSharedMemorySize, smem_bias);
    cudaFuncSetAttribute(attn_kernel, cudaFuncAttributeMaxDynamicSharedMemorySize, smem_attn);

    gemm_qkvg_kernel<<<384, 256>>>(s, qw, qb, kw, vw, gw);
    bias_kernel<<<2048, 256, smem_bias>>>(z, msk, lnw, lnb, zw);
    attn_kernel<<<dim3(16, 16), 256, smem_attn>>>();
    gemm_out_kernel<<<dim3(6, 32), 256>>>(ow, out);
}

// round 12
// speedup vs baseline: 1.8109x; 1.0737x over previous
#include <cuda_runtime.h>

#define S_   512
#define H_   16
#define D_   24
#define DS_  384
#define CZ_  128
#define EPS_ 1e-5f
#define SCALE_ 0.20412414523193152f   // 24^-0.5

// -------- scratch (no allocations allowed) --------
__device__ float g_qt[H_*S_*D_];      // [H][S][D], q pre-scaled by D^-0.5
__device__ float g_kt[H_*S_*D_];
__device__ float g_vt[H_*S_*D_];
__device__ float g_g[S_*DS_];
__device__ float g_o[S_*DS_];
__device__ float g_bias[H_*S_*S_];    // includes seq_mask

// ============================================================
// bias = LN(z) @ z_w^T + mask -> g_bias[H][S][S]
// Block = 128-row z tile. Step C: thread = rows (r, r+64) x 4 heads
// -> 32 FMA per 6 LDS.128. Lane->row stride 132 floats: LDS.128
// phase of 8 lanes covers banks 0..31 exactly (conflict-free).
// ============================================================
#define LDX_ 132

extern __shared__ float smx[];
__global__ __launch_bounds__(256) void bias_kernel(
    const float* __restrict__ z, const float* __restrict__ mask,
    const float* __restrict__ lnw, const float* __restrict__ lnb,
    const float* __restrict__ zw)
{
    float* Y  = smx;                  // 128*132
    float* ZW = smx + 128*LDX_;       // 16*128
    float* MS = ZW + 16*CZ_;          // 128
    const int tid = threadIdx.x;
    const int r0  = blockIdx.x * 128;
    const int i_  = r0 >> 9;
    const int j0  = r0 & 511;

    // ---- A: stage ----
    #pragma unroll
    for (int it = 0; it < 16; it++) {
        const int l = tid + it*256;
        const int row = l >> 5, c4 = l & 31;
        *(float4*)&Y[row*LDX_ + c4*4] =
            *(const float4*)&z[(size_t)(r0 + row)*CZ_ + c4*4];
    }
    #pragma unroll
    for (int it = 0; it < 2; it++)
        ((float4*)ZW)[tid + it*256] = ((const float4*)zw)[tid + it*256];
    if (tid < 32) ((float4*)MS)[tid] = ((const float4*)(mask + j0))[tid];
    __syncthreads();

    // ---- B: layernorm in place (2 threads per row) ----
    {
        const int row  = tid >> 1;
        const int base = (tid & 1) * 64;
        float* xr = &Y[row*LDX_ + base];
        float sum = 0.f, ssq = 0.f;
        #pragma unroll
        for (int c = 0; c < 16; c++) {
            const float4 v = *(const float4*)&xr[c*4];
            sum += v.x + v.y + v.z + v.w;
            ssq += v.x*v.x + v.y*v.y + v.z*v.z + v.w*v.w;
        }
        sum += __shfl_xor_sync(0xffffffffu, sum, 1);
        ssq += __shfl_xor_sync(0xffffffffu, ssq, 1);
        const float mu   = sum * (1.f/CZ_);
        const float var_ = ssq * (1.f/CZ_) - mu*mu;
        const float rinv = rsqrtf(var_ + EPS_);
        #pragma unroll
        for (int c = 0; c < 16; c++) {
            const float4 v  = *(const float4*)&xr[c*4];
            const float4 w4 = *(const float4*)&lnw[base + c*4];
            const float4 b4 = *(const float4*)&lnb[base + c*4];
            float4 y;
            y.x = (v.x - mu)*rinv*w4.x + b4.x;
            y.y = (v.y - mu)*rinv*w4.y + b4.y;
            y.z = (v.z - mu)*rinv*w4.z + b4.z;
            y.w = (v.w - mu)*rinv*w4.w + b4.w;
            *(float4*)&xr[c*4] = y;
        }
    }
    __syncthreads();

    // ---- C: C[128,16] = Y @ zw^T  (thread: rows r,r+64 x heads hb..hb+3) ----
    {
        const int r  = tid & 63;            // = 32*(w&1) + lane
        const int hb = (tid >> 6) * 4;      // warp-uniform head quad
        const float* y0p = &Y[r*LDX_];
        const float* y1p = &Y[(r + 64)*LDX_];
        float acc[2][4] = {};
        #pragma unroll 4
        for (int c4 = 0; c4 < 32; c4++) {
            const float4 y0 = *(const float4*)&y0p[c4*4];
            const float4 y1 = *(const float4*)&y1p[c4*4];
            #pragma unroll
            for (int h = 0; h < 4; h++) {
                const float4 wv = *(const float4*)&ZW[(hb + h)*CZ_ + c4*4];
                acc[0][h] += y0.x*wv.x + y0.y*wv.y + y0.z*wv.z + y0.w*wv.w;
                acc[1][h] += y1.x*wv.x + y1.y*wv.y + y1.z*wv.z + y1.w*wv.w;
            }
        }
        const float mk0 = MS[r], mk1 = MS[r + 64];
        #pragma unroll
        for (int h = 0; h < 4; h++) {
            g_bias[((hb + h)*S_ + i_)*S_ + j0 + r]      = acc[0][h] + mk0;
            g_bias[((hb + h)*S_ + i_)*S_ + j0 + r + 64] = acc[1][h] + mk1;
        }
    }
}

// ============================================================
// QKVG GEMMs: 32x64 tiles, 2x4 microtile, double-buffered.
// 384 blocks -> ~2.6 concurrent blocks/SM, balanced.
// ============================================================
__global__ __launch_bounds__(256) void gemm_qkvg_kernel(
    const float* __restrict__ s,
    const float* __restrict__ qw, const float* __restrict__ qb,
    const float* __restrict__ kw, const float* __restrict__ vw,
    const float* __restrict__ gw)
{
    __shared__ float As[32][36];
    __shared__ float Bs[32][68];
    const int var = blockIdx.z;
    const int m0  = blockIdx.y * 32;
    const int n0  = blockIdx.x * 64;
    const float* W = (var==0)?qw:(var==1)?kw:(var==2)?vw:gw;
    const int tid = threadIdx.x;
    const int tx = tid & 15, ty = tid >> 4;
    const int lk = tid & 31, lm = tid >> 5;
    float acc[2][4] = {};
    float pa[4], pb[8];

    #pragma unroll
    for (int i = 0; i < 4; i++) pa[i] = s[(m0 + lm + 8*i)*DS_ + lk];
    #pragma unroll
    for (int i = 0; i < 8; i++) pb[i] = W[(n0 + lm + 8*i)*DS_ + lk];

    for (int k0 = 0; k0 < DS_; k0 += 32) {
        #pragma unroll
        for (int i = 0; i < 4; i++) As[lk][lm + 8*i] = pa[i];
        #pragma unroll
        for (int i = 0; i < 8; i++) Bs[lk][lm + 8*i] = pb[i];
        __syncthreads();
        if (k0 + 32 < DS_) {
            #pragma unroll
            for (int i = 0; i < 4; i++) pa[i] = s[(m0 + lm + 8*i)*DS_ + k0 + 32 + lk];
            #pragma unroll
            for (int i = 0; i < 8; i++) pb[i] = W[(n0 + lm + 8*i)*DS_ + k0 + 32 + lk];
        }
        #pragma unroll
        for (int kk = 0; kk < 32; kk++) {
            const float2 a  = *(const float2*)&As[kk][ty*2];
            const float4 bv = *(const float4*)&Bs[kk][tx*4];
            acc[0][0] += a.x*bv.x; acc[0][1] += a.x*bv.y; acc[0][2] += a.x*bv.z; acc[0][3] += a.x*bv.w;
            acc[1][0] += a.y*bv.x; acc[1][1] += a.y*bv.y; acc[1][2] += a.y*bv.z; acc[1][3] += a.y*bv.w;
        }
        __syncthreads();
    }

    const int col = n0 + tx*4;
    #pragma unroll
    for (int i = 0; i < 2; i++) {
        const int row = m0 + ty*2 + i;
        float4 rv = make_float4(acc[i][0], acc[i][1], acc[i][2], acc[i][3]);
        if (var == 0) {
            rv.x += qb[col]; rv.y += qb[col+1]; rv.z += qb[col+2]; rv.w += qb[col+3];
            rv.x *= SCALE_; rv.y *= SCALE_; rv.z *= SCALE_; rv.w *= SCALE_;
        }
        if (var == 3) {
            rv.x = 1.f/(1.f+__expf(-rv.x));
            rv.y = 1.f/(1.f+__expf(-rv.y));
            rv.z = 1.f/(1.f+__expf(-rv.z));
            rv.w = 1.f/(1.f+__expf(-rv.w));
            *(float4*)&g_g[row*DS_ + col] = rv;
        } else {
            const int hh = col / D_;
            const int dd = col - hh*D_;
            float* dst = (var==0) ? g_qt : (var==1) ? g_kt : g_vt;
            *(float4*)&dst[(hh*S_ + row)*D_ + dd] = rv;
        }
    }
}

// ============================================================
// attention: block = (head, 32 q-rows), 256 blocks single wave (2/SM).
// PV: thread = (qi=lane, 24 d in regs); warp owns 16-kj stripe per
// 128-tile; partials reduced through smem (stride 25, conflict-free).
// ============================================================
extern __shared__ float sma[];
__global__ __launch_bounds__(256) void attn_kernel()
{
    float* sc   = sma;                       // [32][513]
    float* kv   = sma + 32*513;              // [128][28]
    float* part = sma + 32*513 + 128*28;     // [8][32][25]
    const int h    = blockIdx.y;
    const int qi0  = blockIdx.x * 32;
    const int tid  = threadIdx.x;
    const int lane = tid & 31;
    const int w    = tid >> 5;
    const int qib  = w * 4;

    // q rows in registers
    float qr[4][24];
    #pragma unroll
    for (int i = 0; i < 4; i++) {
        const float4* qp = (const float4*)&g_qt[(h*S_ + qi0 + qib + i)*D_];
        #pragma unroll
        for (int c = 0; c < 6; c++) {
            float4 v = qp[c];
            qr[i][c*4+0] = v.x; qr[i][c*4+1] = v.y; qr[i][c*4+2] = v.z; qr[i][c*4+3] = v.w;
        }
    }

    const float* bias_row = &g_bias[(h*S_ + qi0 + qib)*S_];

    // ---- scores over 4 kj-tiles of 128 ----
    #pragma unroll 1
    for (int tt = 0; tt < 4; tt++) {
        const float4* src = (const float4*)&g_kt[(h*S_ + tt*128)*D_];
        #pragma unroll
        for (int it = 0; it < 3; it++) {
            const int f = tid + it*256;
            const float4 v = src[f];
            const int e0 = f*4;
            const int kjl = e0 / 24, d0 = e0 - kjl*24;
            *(float4*)&kv[kjl*28 + d0] = v;
        }
        __syncthreads();

        #pragma unroll
        for (int ul = 0; ul < 4; ul++) {
            const int kjl = lane + 32*ul;
            const int kj  = tt*128 + kjl;
            const float* kp = &kv[kjl*28];
            float a0 = 0.f, a1 = 0.f, a2 = 0.f, a3 = 0.f;
            #pragma unroll
            for (int c = 0; c < 6; c++) {
                const float4 k4 = *(const float4*)&kp[c*4];
                a0 += qr[0][c*4]*k4.x + qr[0][c*4+1]*k4.y + qr[0][c*4+2]*k4.z + qr[0][c*4+3]*k4.w;
                a1 += qr[1][c*4]*k4.x + qr[1][c*4+1]*k4.y + qr[1][c*4+2]*k4.z + qr[1][c*4+3]*k4.w;
                a2 += qr[2][c*4]*k4.x + qr[2][c*4+1]*k4.y + qr[2][c*4+2]*k4.z + qr[2][c*4+3]*k4.w;
                a3 += qr[3][c*4]*k4.x + qr[3][c*4+1]*k4.y + qr[3][c*4+2]*k4.z + qr[3][c*4+3]*k4.w;
            }
            sc[(qib+0)*513 + kj] = a0 + bias_row[0*S_ + kj];
            sc[(qib+1)*513 + kj] = a1 + bias_row[1*S_ + kj];
            sc[(qib+2)*513 + kj] = a2 + bias_row[2*S_ + kj];
            sc[(qib+3)*513 + kj] = a3 + bias_row[3*S_ + kj];
        }
        __syncthreads();
    }

    // ---- softmax: warp owns its 4 rows ----
    #pragma unroll 1
    for (int rr = 0; rr < 4; rr++) {
        float* p = &sc[(qib + rr)*513];
        float mx = -1e30f;
        #pragma unroll
        for (int t = 0; t < 16; t++) mx = fmaxf(mx, p[lane + 32*t]);
        #pragma unroll
        for (int m = 16; m >= 1; m >>= 1) mx = fmaxf(mx, __shfl_xor_sync(0xffffffffu, mx, m));
        float e[16];
        float sum = 0.f;
        #pragma unroll
        for (int t = 0; t < 16; t++) { e[t] = __expf(p[lane + 32*t] - mx); sum += e[t]; }
        #pragma unroll
        for (int m = 16; m >= 1; m >>= 1) sum += __shfl_xor_sync(0xffffffffu, sum, m);
        const float rinv = 1.f / sum;
        #pragma unroll
        for (int t = 0; t < 16; t++) p[lane + 32*t] = e[t]*rinv;
    }
    __syncthreads();

    // ---- PV: thread = (qi=lane, 24 d); warp = 16-kj stripe per tile ----
    {
        const int qi = lane;
        float acc[24];
        #pragma unroll
        for (int d = 0; d < 24; d++) acc[d] = 0.f;

        #pragma unroll 1
        for (int tt = 0; tt < 4; tt++) {
            const float4* src = (const float4*)&g_vt[(h*S_ + tt*128)*D_];
            #pragma unroll
            for (int it = 0; it < 3; it++) {
                const int f = tid + it*256;
                const float4 v = src[f];
                const int e0 = f*4;
                const int kjl = e0 / 24, d0 = e0 - kjl*24;
                *(float4*)&kv[kjl*28 + d0] = v;
            }
            __syncthreads();

            const float* prow = &sc[qi*513 + tt*128];
            #pragma unroll 2
            for (int kk = 0; kk < 16; kk++) {
                const int kjl = w*16 + kk;
                const float pv = prow[kjl];          // bank (lane+kjl)%32: free
                const float* vp = &kv[kjl*28];       // warp-uniform broadcast
                #pragma unroll
                for (int c = 0; c < 6; c++) {
                    const float4 v4 = *(const float4*)&vp[c*4];
                    acc[c*4+0] += pv*v4.x; acc[c*4+1] += pv*v4.y;
                    acc[c*4+2] += pv*v4.z; acc[c*4+3] += pv*v4.w;
                }
            }
            __syncthreads();
        }

        // partials -> smem (stride 25: bank 25*lane+d, conflict-free)
        float* pp = &part[(w*32 + qi)*25];
        #pragma unroll
        for (int d = 0; d < 24; d++) pp[d] = acc[d];
    }
    __syncthreads();

    // reduce 8 warps and store
    for (int e = tid; e < 32*24; e += 256) {
        const int qi = e / 24, d = e - qi*24;
        float sum = 0.f;
        #pragma unroll
        for (int ww = 0; ww < 8; ww++) sum += part[(ww*32 + qi)*25 + d];
        g_o[(qi0 + qi)*DS_ + h*D_ + d] = sum;
    }
}

// ============================================================
// out = (o * g) @ o_w^T : 32x64 tiles (96 blocks, single wave)
// ============================================================
__global__ __launch_bounds__(256) void gemm_out_kernel(
    const float* __restrict__ W, float* __restrict__ C)
{
    __shared__ float As[32][36];
    __shared__ float Bs[32][68];
    const int n0 = blockIdx.x*64, m0 = blockIdx.y*32;
    const int tid = threadIdx.x;
    const int tx = tid & 15, ty = tid >> 4;
    const int lk = tid & 31, lm = tid >> 5;
    float acc[2][4] = {};
    float pa[4], pb[8];

    #pragma unroll
    for (int i = 0; i < 4; i++) {
        const int ai = (m0 + lm + 8*i)*DS_ + lk;
        pa[i] = g_o[ai] * g_g[ai];
    }
    #pragma unroll
    for (int i = 0; i < 8; i++) pb[i] = W[(n0 + lm + 8*i)*DS_ + lk];

    for (int k0 = 0; k0 < DS_; k0 += 32) {
        #pragma unroll
        for (int i = 0; i < 4; i++) As[lk][lm + 8*i] = pa[i];
        #pragma unroll
        for (int i = 0; i < 8; i++) Bs[lk][lm + 8*i] = pb[i];
        __syncthreads();
        if (k0 + 32 < DS_) {
            #pragma unroll
            for (int i = 0; i < 4; i++) {
                const int ai = (m0 + lm + 8*i)*DS_ + k0 + 32 + lk;
                pa[i] = g_o[ai] * g_g[ai];
            }
            #pragma unroll
            for (int i = 0; i < 8; i++) pb[i] = W[(n0 + lm + 8*i)*DS_ + k0 + 32 + lk];
        }
        #pragma unroll
        for (int kk = 0; kk < 32; kk++) {
            const float2 a  = *(const float2*)&As[kk][ty*2];
            const float4 b = *(const float4*)&Bs[kk][tx*4];
            acc[0][0] += a.x*b.x; acc[0][1] += a.x*b.y; acc[0][2] += a.x*b.z; acc[0][3] += a.x*b.w;
            acc[1][0] += a.y*b.x; acc[1][1] += a.y*b.y; acc[1][2] += a.y*b.z; acc[1][3] += a.y*b.w;
        }
        __syncthreads();
    }
    #pragma unroll
    for (int i = 0; i < 2; i++)
        *(float4*)&C[(m0 + ty*2 + i)*DS_ + n0 + tx*4] =
            make_float4(acc[i][0], acc[i][1], acc[i][2], acc[i][3]);
}

// ============================================================
extern "C" void kernel_launch(void* const* d_in, const int* in_sizes, int n_in,
                              void* d_out, int out_size)
{
    const float* s   = (const float*)d_in[0];
    const float* z   = (const float*)d_in[1];
    const float* msk = (const float*)d_in[2];
    const float* qw  = (const float*)d_in[3];
    const float* qb  = (const float*)d_in[4];
    const float* kw  = (const float*)d_in[5];
    const float* vw  = (const float*)d_in[6];
    const float* gw  = (const float*)d_in[7];
    const float* ow  = (const float*)d_in[8];
    const float* lnw = (const float*)d_in[9];
    const float* lnb = (const float*)d_in[10];
    const float* zw  = (const float*)d_in[11];
    float* out = (float*)d_out;

    const int smem_bias = (128*LDX_ + 16*CZ_ + 128) * 4;        // 76352 B
    const int smem_attn = (32*513 + 128*28 + 8*32*25) * 4;      // 105600 B
    cudaFuncSetAttribute(bias_kernel, cudaFuncAttributeMaxDynamicSharedMemorySize, smem_bias);
    cudaFuncSetAttribute(attn_kernel, cudaFuncAttributeMaxDynamicSharedMemorySize, smem_attn);

    gemm_qkvg_kernel<<<dim3(6, 16, 4), 256>>>(s, qw, qb, kw, vw, gw);
    bias_kernel<<<2048, 256, smem_bias>>>(z, msk, lnw, lnb, zw);
    attn_kernel<<<dim3(16, 16), 256, smem_attn>>>();
    gemm_out_kernel<<<dim3(6, 16), 256>>>(ow, out);
}